// round 13
// baseline (speedup 1.0000x reference)
#include <cuda_runtime.h>
#include <cuda_fp16.h>
#include <math.h>

#define NNODES 50000
#define NEDGES 1600000
#define HDIM   64
#define EMBDIM 192
#define CDIM   16
#define NPAD   57344   // 7 * 8192, padded for vectorized scan

#define GEMM_BLOCKS 391                       // ceil(50000/128)
#define HIST_BLOCKS 1563                      // ceil((NEDGES/4)/256)
#define AGG_BLOCKS  888                       // 6 blocks/SM x 148 SMs (persistent)
#define AGG_WARPS   (AGG_BLOCKS * 8)

// ---------------- scratch (static device globals; no allocation) -------------
__device__ __align__(128) __half d_h[NNODES * HDIM];    // per-layer GEMM output (fp16), row = 1 L2 line
__device__ __align__(16) __half d_emb[NNODES * EMBDIM]; // concat of 3 layer outputs (fp16)
__device__ float d_dis[NNODES];                         // D^-1/2
__device__ __align__(16) int d_count[NPAD];             // zeroed at load; self-cleaned by k_scan
__device__ __align__(16) int d_rowptr[NNODES + 8];
__device__ __align__(16) int d_cursor[NNODES + 8];
__device__ unsigned d_csre[NEDGES];                     // {w_fp16:16 | col:16}

// ---------------- GEMM body (device fn, used by fused + standalone) ----------
#define XPAD 72
__device__ __forceinline__ void gemm_body(const float* __restrict__ xf,
                                          int inoff, int istride,
                                          const float* __restrict__ W,
                                          int bidx) {
    __shared__ __align__(16) __half Xs[64 * XPAD];
    __shared__ __align__(16) __half Ws[64 * XPAD];
    int tid = threadIdx.x;

    // load + convert W once per block: thread -> 16 consecutive floats
    {
        int r = tid >> 2, c0 = (tid & 3) * 16;
        const float4* wp = (const float4*)&W[r * 64 + c0];
#pragma unroll
        for (int q = 0; q < 4; q++) {
            float4 wv = wp[q];
            __half2 h0 = __floats2half2_rn(wv.x, wv.y);
            __half2 h1 = __floats2half2_rn(wv.z, wv.w);
            uint2 st; st.x = *(unsigned*)&h0; st.y = *(unsigned*)&h1;
            *(uint2*)&Ws[r * XPAD + c0 + q * 4] = st;
        }
    }

    int warp = tid >> 5, lane = tid & 31;
    int Mtile = (warp & 3) * 16;
    int Nbase = (warp >> 2) * 32;

#pragma unroll 1
    for (int rep = 0; rep < 2; rep++) {
        int bm = bidx * 128 + rep * 64;
        // load X tile (64 rows)
        if (xf) {
            int r = tid >> 2, c0 = (tid & 3) * 16;
            int gr = bm + r;
            if (gr < NNODES) {
                const float4* xp = (const float4*)&xf[gr * istride + inoff + c0];
#pragma unroll
                for (int q = 0; q < 4; q++) {
                    float4 xv = xp[q];
                    __half2 h0 = __floats2half2_rn(xv.x, xv.y);
                    __half2 h1 = __floats2half2_rn(xv.z, xv.w);
                    uint2 st; st.x = *(unsigned*)&h0; st.y = *(unsigned*)&h1;
                    *(uint2*)&Xs[r * XPAD + c0 + q * 4] = st;
                }
            } else {
                uint2 z = make_uint2(0u, 0u);
#pragma unroll
                for (int q = 0; q < 4; q++)
                    *(uint2*)&Xs[r * XPAD + c0 + q * 4] = z;
            }
        } else {
            const __half* xh = d_emb;   // device-side symbol reference
            int r = tid >> 2, c0 = (tid & 3) * 16;
            int gr = bm + r;
            if (gr < NNODES) {
                const uint4* xp = (const uint4*)&xh[gr * istride + inoff + c0];
                uint4 v0 = xp[0];
                uint4 v1 = xp[1];
                *(uint2*)&Xs[r * XPAD + c0]      = make_uint2(v0.x, v0.y);
                *(uint2*)&Xs[r * XPAD + c0 + 4]  = make_uint2(v0.z, v0.w);
                *(uint2*)&Xs[r * XPAD + c0 + 8]  = make_uint2(v1.x, v1.y);
                *(uint2*)&Xs[r * XPAD + c0 + 12] = make_uint2(v1.z, v1.w);
            } else {
                uint2 z = make_uint2(0u, 0u);
#pragma unroll
                for (int q = 0; q < 4; q++)
                    *(uint2*)&Xs[r * XPAD + c0 + q * 4] = z;
            }
        }
        __syncthreads();

        float acc[4][4];
#pragma unroll
        for (int j = 0; j < 4; j++)
#pragma unroll
            for (int q = 0; q < 4; q++) acc[j][q] = 0.0f;

#pragma unroll
        for (int kk = 0; kk < 4; kk++) {
            unsigned a0, a1, a2, a3;
            {
                int row = Mtile + (lane & 15);
                int col = kk * 16 + (lane >> 4) * 8;
                unsigned addr = (unsigned)__cvta_generic_to_shared(&Xs[row * XPAD + col]);
                asm volatile("ldmatrix.sync.aligned.m8n8.x4.shared.b16 {%0,%1,%2,%3}, [%4];"
                             : "=r"(a0), "=r"(a1), "=r"(a2), "=r"(a3) : "r"(addr));
            }
#pragma unroll
            for (int j = 0; j < 4; j++) {
                int n0 = Nbase + j * 8;
                unsigned b0, b1;
                {
                    int row = kk * 16 + (lane & 15);
                    unsigned addr = (unsigned)__cvta_generic_to_shared(&Ws[row * XPAD + n0]);
                    asm volatile("ldmatrix.sync.aligned.m8n8.x2.trans.shared.b16 {%0,%1}, [%2];"
                                 : "=r"(b0), "=r"(b1) : "r"(addr));
                }
                asm volatile("mma.sync.aligned.m16n8k16.row.col.f32.f16.f16.f32 "
                             "{%0,%1,%2,%3},{%4,%5,%6,%7},{%8,%9},{%0,%1,%2,%3};"
                             : "+f"(acc[j][0]), "+f"(acc[j][1]), "+f"(acc[j][2]), "+f"(acc[j][3])
                             : "r"(a0), "r"(a1), "r"(a2), "r"(a3), "r"(b0), "r"(b1));
            }
        }

        // epilogue: write fp16 to d_h
        int r0 = bm + Mtile + (lane >> 2);
        int cb = (lane & 3) * 2;
#pragma unroll
        for (int j = 0; j < 4; j++) {
            int col = Nbase + j * 8 + cb;
            if (r0 < NNODES) {
                __half2 p = __floats2half2_rn(acc[j][0], acc[j][1]);
                *(__half2*)&d_h[r0 * 64 + col] = p;
            }
            if (r0 + 8 < NNODES) {
                __half2 p = __floats2half2_rn(acc[j][2], acc[j][3]);
                *(__half2*)&d_h[(r0 + 8) * 64 + col] = p;
            }
        }
        __syncthreads();   // protect Xs before next rep overwrites
    }
}

// ---------------- fused gemm1 + histogram (independent work, one launch) -----
__global__ void __launch_bounds__(256) k_g1hist(const float* __restrict__ xf,
                                                const float* __restrict__ W,
                                                const int* __restrict__ ei) {
    if (blockIdx.x < GEMM_BLOCKS) {
        gemm_body(xf, 0, HDIM, W, blockIdx.x);
    } else {
        int t = (blockIdx.x - GEMM_BLOCKS) * 256 + threadIdx.x;
        if (t < NEDGES / 4) {
            int4 r = ((const int4*)ei)[t];
            atomicAdd(&d_count[r.x], 1);
            atomicAdd(&d_count[r.y], 1);
            atomicAdd(&d_count[r.z], 1);
            atomicAdd(&d_count[r.w], 1);
        }
    }
}

// standalone GEMM for layers 2/3
__global__ void __launch_bounds__(256) k_gemm(const float* __restrict__ xf,
                                              int inoff, int istride,
                                              const float* __restrict__ W) {
    gemm_body(xf, inoff, istride, W, blockIdx.x);
}

// single-block scan: 1024 threads x 8 elements x 7 tiles (padded counts are 0).
// Self-cleaning: zeroes d_count after reading, so no memset node is needed
// on replay (module load zero-inits; every run leaves counts at 0).
__global__ void __launch_bounds__(1024) k_scan() {
    __shared__ int wsum[32];
    __shared__ int blktot;
    int tid = threadIdx.x;
    int lane = tid & 31, wid = tid >> 5;
    int carry = 0;
#pragma unroll 1
    for (int t = 0; t < 7; t++) {
        int i0 = t * 8192 + tid * 8;
        int4 c0 = *(const int4*)&d_count[i0];
        int4 c1 = *(const int4*)&d_count[i0 + 4];
        int p0 = c0.x;
        int p1 = p0 + c0.y;
        int p2 = p1 + c0.z;
        int p3 = p2 + c0.w;
        int p4 = p3 + c1.x;
        int p5 = p4 + c1.y;
        int p6 = p5 + c1.z;
        int p7 = p6 + c1.w;          // thread total
        int v = p7;
#pragma unroll
        for (int o = 1; o < 32; o <<= 1) {
            int tv = __shfl_up_sync(0xffffffffu, v, o);
            if (lane >= o) v += tv;
        }
        if (lane == 31) wsum[wid] = v;
        __syncthreads();
        if (wid == 0) {
            int w = wsum[lane];
#pragma unroll
            for (int o = 1; o < 32; o <<= 1) {
                int tw = __shfl_up_sync(0xffffffffu, w, o);
                if (lane >= o) w += tw;
            }
            wsum[lane] = w;
            if (lane == 31) blktot = w;
        }
        __syncthreads();
        int base = carry + ((wid > 0) ? wsum[wid - 1] : 0) + (v - p7); // exclusive
        if (i0 < NNODES) {           // NNODES % 8 == 0 -> whole group valid
            int4 r0 = make_int4(base, base + p0, base + p1, base + p2);
            int4 r1 = make_int4(base + p3, base + p4, base + p5, base + p6);
            *(int4*)&d_rowptr[i0]     = r0;
            *(int4*)&d_rowptr[i0 + 4] = r1;
            *(int4*)&d_cursor[i0]     = r0;
            *(int4*)&d_cursor[i0 + 4] = r1;
            float4 q0, q1;
            q0.x = rsqrtf((float)(c0.x + 1)); q0.y = rsqrtf((float)(c0.y + 1));
            q0.z = rsqrtf((float)(c0.z + 1)); q0.w = rsqrtf((float)(c0.w + 1));
            q1.x = rsqrtf((float)(c1.x + 1)); q1.y = rsqrtf((float)(c1.y + 1));
            q1.z = rsqrtf((float)(c1.z + 1)); q1.w = rsqrtf((float)(c1.w + 1));
            *(float4*)&d_dis[i0]     = q0;
            *(float4*)&d_dis[i0 + 4] = q1;
            // self-clean for next replay
            int4 z = make_int4(0, 0, 0, 0);
            *(int4*)&d_count[i0]     = z;
            *(int4*)&d_count[i0 + 4] = z;
        }
        carry += blktot;
        __syncthreads();
    }
    if (tid == 0) d_rowptr[NNODES] = NEDGES;
}

// scatter packed edge records, 2 edges per thread (NEDGES % 2 == 0)
__global__ void k_scatter(const int* __restrict__ ei) {
    int t = blockIdx.x * blockDim.x + threadIdx.x;
    if (t < NEDGES / 2) {
        int2 r = ((const int2*)ei)[t];
        int2 c = ((const int2*)(ei + NEDGES))[t];
        float w0 = d_dis[r.x] * d_dis[c.x];
        float w1 = d_dis[r.y] * d_dis[c.y];
        unsigned wb0 = (unsigned)__half_as_ushort(__float2half_rn(w0));
        unsigned wb1 = (unsigned)__half_as_ushort(__float2half_rn(w1));
        int p0 = atomicAdd(&d_cursor[r.x], 1);
        d_csre[p0] = (unsigned)c.x | (wb0 << 16);
        int p1 = atomicAdd(&d_cursor[r.y], 1);
        d_csre[p1] = (unsigned)c.y | (wb1 << 16);
    }
}

// ---------------- fused aggregate + self-loop + bias + relu + l2norm --------
// PERSISTENT: fixed grid (888 blocks = 6/SM), each warp strides over nodes.
// Records prefetched 32-at-a-time coalesced + shfl broadcast; HFMA2 inner
// accumulation flushed to fp32 per 32-edge chunk. Padded records are 0.
__global__ void __launch_bounds__(256) k_agg(const float* __restrict__ bias, int loff) {
    int warp0 = (blockIdx.x * blockDim.x + threadIdx.x) >> 5;
    int lane = threadIdx.x & 31;
    int g = lane >> 3, s = lane & 7;
    const __half2 hz = __half2half2(__ushort_as_half((unsigned short)0));

    for (int node = warp0; node < NNODES; node += AGG_WARPS) {
        int s0 = d_rowptr[node];
        int cnt = d_rowptr[node + 1] - s0;

        float a0 = 0.f, a1 = 0.f, a2 = 0.f, a3 = 0.f, a4 = 0.f, a5 = 0.f, a6 = 0.f, a7 = 0.f;
        for (int base = 0; base < cnt; base += 32) {
            int m = cnt - base;
            if (m > 32) m = 32;
            unsigned myrec = (lane < m) ? d_csre[s0 + base + lane] : 0u;
            int T = (m + 3) >> 2;                 // warp-uniform trip count (<= 8)
            __half2 A0 = hz, A1 = hz, A2 = hz, A3 = hz;
#pragma unroll 8
            for (int k = 0; k < T; k++) {
                unsigned rec = __shfl_sync(0xffffffffu, myrec, 4 * k + g);
                int c = (int)(rec & 0xffffu);
                __half2 rh = *(__half2*)&rec;
                __half2 w2 = __half2half2(__high2half(rh));   // splat high half
                uint4 hv = *(const uint4*)&d_h[c * 64 + s * 8];
                A0 = __hfma2(*(const __half2*)&hv.x, w2, A0);
                A1 = __hfma2(*(const __half2*)&hv.y, w2, A1);
                A2 = __hfma2(*(const __half2*)&hv.z, w2, A2);
                A3 = __hfma2(*(const __half2*)&hv.w, w2, A3);
            }
            float2 t0 = __half22float2(A0);
            float2 t1 = __half22float2(A1);
            float2 t2 = __half22float2(A2);
            float2 t3 = __half22float2(A3);
            a0 += t0.x; a1 += t0.y;
            a2 += t1.x; a3 += t1.y;
            a4 += t2.x; a5 += t2.y;
            a6 += t3.x; a7 += t3.y;
        }
        // reduce across the 4 groups
#pragma unroll
        for (int o = 8; o <= 16; o <<= 1) {
            a0 += __shfl_xor_sync(0xffffffffu, a0, o);
            a1 += __shfl_xor_sync(0xffffffffu, a1, o);
            a2 += __shfl_xor_sync(0xffffffffu, a2, o);
            a3 += __shfl_xor_sync(0xffffffffu, a3, o);
            a4 += __shfl_xor_sync(0xffffffffu, a4, o);
            a5 += __shfl_xor_sync(0xffffffffu, a5, o);
            a6 += __shfl_xor_sync(0xffffffffu, a6, o);
            a7 += __shfl_xor_sync(0xffffffffu, a7, o);
        }
        if (g == 0) {
            float di = d_dis[node];
            float ws = di * di;                     // self-loop weight (fp32 path)
            uint4 hv = *(const uint4*)&d_h[node * 64 + s * 8];
            float2 f0 = __half22float2(*(const __half2*)&hv.x);
            float2 f1 = __half22float2(*(const __half2*)&hv.y);
            float2 f2 = __half22float2(*(const __half2*)&hv.z);
            float2 f3 = __half22float2(*(const __half2*)&hv.w);
            a0 += f0.x * ws; a1 += f0.y * ws;
            a2 += f1.x * ws; a3 += f1.y * ws;
            a4 += f2.x * ws; a5 += f2.y * ws;
            a6 += f3.x * ws; a7 += f3.y * ws;
            float4 bv0 = *(const float4*)&bias[s * 8];
            float4 bv1 = *(const float4*)&bias[s * 8 + 4];
            a0 = fmaxf(a0 + bv0.x, 0.f); a1 = fmaxf(a1 + bv0.y, 0.f);
            a2 = fmaxf(a2 + bv0.z, 0.f); a3 = fmaxf(a3 + bv0.w, 0.f);
            a4 = fmaxf(a4 + bv1.x, 0.f); a5 = fmaxf(a5 + bv1.y, 0.f);
            a6 = fmaxf(a6 + bv1.z, 0.f); a7 = fmaxf(a7 + bv1.w, 0.f);
            float ss = a0 * a0 + a1 * a1 + a2 * a2 + a3 * a3
                     + a4 * a4 + a5 * a5 + a6 * a6 + a7 * a7;
#pragma unroll
            for (int o = 1; o <= 4; o <<= 1)
                ss += __shfl_xor_sync(0x000000ffu, ss, o);
            float inv = 1.0f / fmaxf(sqrtf(ss), 1e-12f);
            a0 *= inv; a1 *= inv; a2 *= inv; a3 *= inv;
            a4 *= inv; a5 *= inv; a6 *= inv; a7 *= inv;
            __half2 p0 = __floats2half2_rn(a0, a1);
            __half2 p1 = __floats2half2_rn(a2, a3);
            __half2 p2 = __floats2half2_rn(a4, a5);
            __half2 p3 = __floats2half2_rn(a6, a7);
            uint4 ov;
            ov.x = *(unsigned*)&p0; ov.y = *(unsigned*)&p1;
            ov.z = *(unsigned*)&p2; ov.w = *(unsigned*)&p3;
            *(uint4*)&d_emb[node * EMBDIM + loff + s * 8] = ov;
        }
    }
}

// ---------------- final linear + log_softmax --------------------------------
__global__ void __launch_bounds__(256) k_final(const float* __restrict__ Wl,
                                               const float* __restrict__ bl,
                                               float* __restrict__ out) {
    __shared__ __align__(16) float Ws[EMBDIM * CDIM];
    __shared__ float bs[CDIM];
    int tid = threadIdx.x;
    for (int idx = tid; idx < EMBDIM * CDIM; idx += 256) Ws[idx] = Wl[idx];
    if (tid < CDIM) bs[tid] = bl[tid];
    __syncthreads();
    int i = blockIdx.x * 256 + tid;
    if (i >= NNODES) return;
    float acc[CDIM];
#pragma unroll
    for (int j = 0; j < CDIM; j++) acc[j] = bs[j];
    const uint4* erow = (const uint4*)&d_emb[i * EMBDIM];
#pragma unroll 4
    for (int kc = 0; kc < 24; kc++) {          // 24 chunks of 8 halfs
        uint4 hv = erow[kc];
        float2 f[4];
        f[0] = __half22float2(*(const __half2*)&hv.x);
        f[1] = __half22float2(*(const __half2*)&hv.y);
        f[2] = __half22float2(*(const __half2*)&hv.z);
        f[3] = __half22float2(*(const __half2*)&hv.w);
        int kb = kc * 8;
#pragma unroll
        for (int u = 0; u < 4; u++) {
            float ex = f[u].x, ey = f[u].y;
            const float* w0 = &Ws[(kb + 2 * u) * CDIM];
            const float* w1 = w0 + CDIM;
#pragma unroll
            for (int j = 0; j < CDIM; j++)
                acc[j] += ex * w0[j] + ey * w1[j];
        }
    }
    float m = acc[0];
#pragma unroll
    for (int j = 1; j < CDIM; j++) m = fmaxf(m, acc[j]);
    float sum = 0.f;
#pragma unroll
    for (int j = 0; j < CDIM; j++) sum += __expf(acc[j] - m);
    float lse = m + __logf(sum);
#pragma unroll
    for (int j = 0; j < CDIM; j++) out[i * CDIM + j] = acc[j] - lse;
}

// ---------------- launch -----------------------------------------------------
extern "C" void kernel_launch(void* const* d_in, const int* in_sizes, int n_in,
                              void* d_out, int out_size) {
    const float* x    = (const float*)d_in[0];
    const int*   ei   = (const int*)d_in[1];
    const float* W1   = (const float*)d_in[2];
    const float* b1   = (const float*)d_in[3];
    const float* W2   = (const float*)d_in[4];
    const float* b2   = (const float*)d_in[5];
    const float* W3   = (const float*)d_in[6];
    const float* b3   = (const float*)d_in[7];
    const float* Wlin = (const float*)d_in[8];
    const float* blin = (const float*)d_in[9];
    float* out = (float*)d_out;

    // fused: gemm1 (blocks 0..390) + histogram (blocks 391..) in ONE launch
    // (d_count is zero at entry: zero-init at load, self-cleaned by k_scan)
    k_g1hist<<<GEMM_BLOCKS + HIST_BLOCKS, 256>>>(x, W1, ei);
    k_scan<<<1, 1024>>>();
    k_scatter<<<(NEDGES / 2 + 255) / 256, 256>>>(ei);

    k_agg<<<AGG_BLOCKS, 256>>>(b1, 0);
    // layer 2 (fp16 emb slice 0, selected in device code)
    k_gemm<<<GEMM_BLOCKS, 256>>>(nullptr, 0, EMBDIM, W2);
    k_agg<<<AGG_BLOCKS, 256>>>(b2, 64);
    // layer 3 (fp16 emb slice 1)
    k_gemm<<<GEMM_BLOCKS, 256>>>(nullptr, 64, EMBDIM, W3);
    k_agg<<<AGG_BLOCKS, 256>>>(b3, 128);

    k_final<<<(NNODES + 255) / 256, 256>>>(Wlin, blin, out);
}

// round 15
// speedup vs baseline: 1.1573x; 1.1573x over previous
#include <cuda_runtime.h>
#include <cuda_fp16.h>
#include <math.h>

#define NNODES 50000
#define NEDGES 1600000
#define HDIM   64
#define EMBDIM 192
#define CDIM   16
#define NPAD   57344   // 7 * 8192, padded for vectorized scan

#define GEMM_BLOCKS 391                       // ceil(50000/128)
#define HIST_BLOCKS 1563                      // ceil((NEDGES/4)/256)

// ---------------- scratch (static device globals; no allocation) -------------
__device__ __align__(128) __half d_h[NNODES * HDIM];    // per-layer GEMM output (fp16), row = 1 L2 line
__device__ __align__(16) __half d_emb[NNODES * EMBDIM]; // concat of 3 layer outputs (fp16)
__device__ float d_dis[NNODES];                         // D^-1/2
__device__ __align__(16) int d_count[NPAD];             // zeroed at load; self-cleaned by k_scan
__device__ __align__(16) int d_rowptr[NNODES + 8];
__device__ __align__(16) int d_cursor[NNODES + 8];
__device__ unsigned d_csre[NEDGES];                     // {w_fp16:16 | col:16}

// ---------------- GEMM body (device fn, used by fused + standalone) ----------
#define XPAD 72
__device__ __forceinline__ void gemm_body(const float* __restrict__ xf,
                                          int inoff, int istride,
                                          const float* __restrict__ W,
                                          int bidx) {
    __shared__ __align__(16) __half Xs[64 * XPAD];
    __shared__ __align__(16) __half Ws[64 * XPAD];
    int tid = threadIdx.x;

    // load + convert W once per block: thread -> 16 consecutive floats
    {
        int r = tid >> 2, c0 = (tid & 3) * 16;
        const float4* wp = (const float4*)&W[r * 64 + c0];
#pragma unroll
        for (int q = 0; q < 4; q++) {
            float4 wv = wp[q];
            __half2 h0 = __floats2half2_rn(wv.x, wv.y);
            __half2 h1 = __floats2half2_rn(wv.z, wv.w);
            uint2 st; st.x = *(unsigned*)&h0; st.y = *(unsigned*)&h1;
            *(uint2*)&Ws[r * XPAD + c0 + q * 4] = st;
        }
    }

    int warp = tid >> 5, lane = tid & 31;
    int Mtile = (warp & 3) * 16;
    int Nbase = (warp >> 2) * 32;

#pragma unroll 1
    for (int rep = 0; rep < 2; rep++) {
        int bm = bidx * 128 + rep * 64;
        // load X tile (64 rows)
        if (xf) {
            int r = tid >> 2, c0 = (tid & 3) * 16;
            int gr = bm + r;
            if (gr < NNODES) {
                const float4* xp = (const float4*)&xf[gr * istride + inoff + c0];
#pragma unroll
                for (int q = 0; q < 4; q++) {
                    float4 xv = xp[q];
                    __half2 h0 = __floats2half2_rn(xv.x, xv.y);
                    __half2 h1 = __floats2half2_rn(xv.z, xv.w);
                    uint2 st; st.x = *(unsigned*)&h0; st.y = *(unsigned*)&h1;
                    *(uint2*)&Xs[r * XPAD + c0 + q * 4] = st;
                }
            } else {
                uint2 z = make_uint2(0u, 0u);
#pragma unroll
                for (int q = 0; q < 4; q++)
                    *(uint2*)&Xs[r * XPAD + c0 + q * 4] = z;
            }
        } else {
            const __half* xh = d_emb;   // device-side symbol reference
            int r = tid >> 2, c0 = (tid & 3) * 16;
            int gr = bm + r;
            if (gr < NNODES) {
                const uint4* xp = (const uint4*)&xh[gr * istride + inoff + c0];
                uint4 v0 = xp[0];
                uint4 v1 = xp[1];
                *(uint2*)&Xs[r * XPAD + c0]      = make_uint2(v0.x, v0.y);
                *(uint2*)&Xs[r * XPAD + c0 + 4]  = make_uint2(v0.z, v0.w);
                *(uint2*)&Xs[r * XPAD + c0 + 8]  = make_uint2(v1.x, v1.y);
                *(uint2*)&Xs[r * XPAD + c0 + 12] = make_uint2(v1.z, v1.w);
            } else {
                uint2 z = make_uint2(0u, 0u);
#pragma unroll
                for (int q = 0; q < 4; q++)
                    *(uint2*)&Xs[r * XPAD + c0 + q * 4] = z;
            }
        }
        __syncthreads();

        float acc[4][4];
#pragma unroll
        for (int j = 0; j < 4; j++)
#pragma unroll
            for (int q = 0; q < 4; q++) acc[j][q] = 0.0f;

#pragma unroll
        for (int kk = 0; kk < 4; kk++) {
            unsigned a0, a1, a2, a3;
            {
                int row = Mtile + (lane & 15);
                int col = kk * 16 + (lane >> 4) * 8;
                unsigned addr = (unsigned)__cvta_generic_to_shared(&Xs[row * XPAD + col]);
                asm volatile("ldmatrix.sync.aligned.m8n8.x4.shared.b16 {%0,%1,%2,%3}, [%4];"
                             : "=r"(a0), "=r"(a1), "=r"(a2), "=r"(a3) : "r"(addr));
            }
#pragma unroll
            for (int j = 0; j < 4; j++) {
                int n0 = Nbase + j * 8;
                unsigned b0, b1;
                {
                    int row = kk * 16 + (lane & 15);
                    unsigned addr = (unsigned)__cvta_generic_to_shared(&Ws[row * XPAD + n0]);
                    asm volatile("ldmatrix.sync.aligned.m8n8.x2.trans.shared.b16 {%0,%1}, [%2];"
                                 : "=r"(b0), "=r"(b1) : "r"(addr));
                }
                asm volatile("mma.sync.aligned.m16n8k16.row.col.f32.f16.f16.f32 "
                             "{%0,%1,%2,%3},{%4,%5,%6,%7},{%8,%9},{%0,%1,%2,%3};"
                             : "+f"(acc[j][0]), "+f"(acc[j][1]), "+f"(acc[j][2]), "+f"(acc[j][3])
                             : "r"(a0), "r"(a1), "r"(a2), "r"(a3), "r"(b0), "r"(b1));
            }
        }

        // epilogue: write fp16 to d_h
        int r0 = bm + Mtile + (lane >> 2);
        int cb = (lane & 3) * 2;
#pragma unroll
        for (int j = 0; j < 4; j++) {
            int col = Nbase + j * 8 + cb;
            if (r0 < NNODES) {
                __half2 p = __floats2half2_rn(acc[j][0], acc[j][1]);
                *(__half2*)&d_h[r0 * 64 + col] = p;
            }
            if (r0 + 8 < NNODES) {
                __half2 p = __floats2half2_rn(acc[j][2], acc[j][3]);
                *(__half2*)&d_h[(r0 + 8) * 64 + col] = p;
            }
        }
        __syncthreads();   // protect Xs before next rep overwrites
    }
}

// ---------------- fused gemm1 + histogram (independent work, one launch) -----
__global__ void __launch_bounds__(256) k_g1hist(const float* __restrict__ xf,
                                                const float* __restrict__ W,
                                                const int* __restrict__ ei) {
    if (blockIdx.x < GEMM_BLOCKS) {
        gemm_body(xf, 0, HDIM, W, blockIdx.x);
    } else {
        int t = (blockIdx.x - GEMM_BLOCKS) * 256 + threadIdx.x;
        if (t < NEDGES / 4) {
            int4 r = ((const int4*)ei)[t];
            atomicAdd(&d_count[r.x], 1);
            atomicAdd(&d_count[r.y], 1);
            atomicAdd(&d_count[r.z], 1);
            atomicAdd(&d_count[r.w], 1);
        }
    }
}

// standalone GEMM for layers 2/3
__global__ void __launch_bounds__(256) k_gemm(const float* __restrict__ xf,
                                              int inoff, int istride,
                                              const float* __restrict__ W) {
    gemm_body(xf, inoff, istride, W, blockIdx.x);
}

// single-block scan: 1024 threads x 8 elements x 7 tiles (padded counts are 0).
// Self-cleaning: zeroes d_count after reading, so no memset node is needed
// on replay (module load zero-inits; every run leaves counts at 0).
__global__ void __launch_bounds__(1024) k_scan() {
    __shared__ int wsum[32];
    __shared__ int blktot;
    int tid = threadIdx.x;
    int lane = tid & 31, wid = tid >> 5;
    int carry = 0;
#pragma unroll 1
    for (int t = 0; t < 7; t++) {
        int i0 = t * 8192 + tid * 8;
        int4 c0 = *(const int4*)&d_count[i0];
        int4 c1 = *(const int4*)&d_count[i0 + 4];
        int p0 = c0.x;
        int p1 = p0 + c0.y;
        int p2 = p1 + c0.z;
        int p3 = p2 + c0.w;
        int p4 = p3 + c1.x;
        int p5 = p4 + c1.y;
        int p6 = p5 + c1.z;
        int p7 = p6 + c1.w;          // thread total
        int v = p7;
#pragma unroll
        for (int o = 1; o < 32; o <<= 1) {
            int tv = __shfl_up_sync(0xffffffffu, v, o);
            if (lane >= o) v += tv;
        }
        if (lane == 31) wsum[wid] = v;
        __syncthreads();
        if (wid == 0) {
            int w = wsum[lane];
#pragma unroll
            for (int o = 1; o < 32; o <<= 1) {
                int tw = __shfl_up_sync(0xffffffffu, w, o);
                if (lane >= o) w += tw;
            }
            wsum[lane] = w;
            if (lane == 31) blktot = w;
        }
        __syncthreads();
        int base = carry + ((wid > 0) ? wsum[wid - 1] : 0) + (v - p7); // exclusive
        if (i0 < NNODES) {           // NNODES % 8 == 0 -> whole group valid
            int4 r0 = make_int4(base, base + p0, base + p1, base + p2);
            int4 r1 = make_int4(base + p3, base + p4, base + p5, base + p6);
            *(int4*)&d_rowptr[i0]     = r0;
            *(int4*)&d_rowptr[i0 + 4] = r1;
            *(int4*)&d_cursor[i0]     = r0;
            *(int4*)&d_cursor[i0 + 4] = r1;
            float4 q0, q1;
            q0.x = rsqrtf((float)(c0.x + 1)); q0.y = rsqrtf((float)(c0.y + 1));
            q0.z = rsqrtf((float)(c0.z + 1)); q0.w = rsqrtf((float)(c0.w + 1));
            q1.x = rsqrtf((float)(c1.x + 1)); q1.y = rsqrtf((float)(c1.y + 1));
            q1.z = rsqrtf((float)(c1.z + 1)); q1.w = rsqrtf((float)(c1.w + 1));
            *(float4*)&d_dis[i0]     = q0;
            *(float4*)&d_dis[i0 + 4] = q1;
            // self-clean for next replay
            int4 z = make_int4(0, 0, 0, 0);
            *(int4*)&d_count[i0]     = z;
            *(int4*)&d_count[i0 + 4] = z;
        }
        carry += blktot;
        __syncthreads();
    }
    if (tid == 0) d_rowptr[NNODES] = NEDGES;
}

// scatter packed edge records, 2 edges per thread (NEDGES % 2 == 0)
__global__ void k_scatter(const int* __restrict__ ei) {
    int t = blockIdx.x * blockDim.x + threadIdx.x;
    if (t < NEDGES / 2) {
        int2 r = ((const int2*)ei)[t];
        int2 c = ((const int2*)(ei + NEDGES))[t];
        float w0 = d_dis[r.x] * d_dis[c.x];
        float w1 = d_dis[r.y] * d_dis[c.y];
        unsigned wb0 = (unsigned)__half_as_ushort(__float2half_rn(w0));
        unsigned wb1 = (unsigned)__half_as_ushort(__float2half_rn(w1));
        int p0 = atomicAdd(&d_cursor[r.x], 1);
        d_csre[p0] = (unsigned)c.x | (wb0 << 16);
        int p1 = atomicAdd(&d_cursor[r.y], 1);
        d_csre[p1] = (unsigned)c.y | (wb1 << 16);
    }
}

// ---------------- fused aggregate + self-loop + bias + relu + l2norm --------
// NON-PERSISTENT (one warp per node, HW scheduler balances irregular degrees).
// Records prefetched 32-at-a-time coalesced + shfl broadcast; HFMA2 inner
// accumulation flushed to fp32 per 32-edge chunk. Padded records are 0.
__global__ void __launch_bounds__(256, 6) k_agg(const float* __restrict__ bias, int loff) {
    int node = (blockIdx.x * blockDim.x + threadIdx.x) >> 5;
    if (node >= NNODES) return;
    int lane = threadIdx.x & 31;
    int g = lane >> 3, s = lane & 7;
    int s0 = d_rowptr[node];
    int cnt = d_rowptr[node + 1] - s0;
    const __half2 hz = __half2half2(__ushort_as_half((unsigned short)0));

    float a0 = 0.f, a1 = 0.f, a2 = 0.f, a3 = 0.f, a4 = 0.f, a5 = 0.f, a6 = 0.f, a7 = 0.f;
    for (int base = 0; base < cnt; base += 32) {
        int m = cnt - base;
        if (m > 32) m = 32;
        unsigned myrec = (lane < m) ? d_csre[s0 + base + lane] : 0u;
        int T = (m + 3) >> 2;                 // warp-uniform trip count (<= 8)
        __half2 A0 = hz, A1 = hz, A2 = hz, A3 = hz;
#pragma unroll 8
        for (int k = 0; k < T; k++) {
            unsigned rec = __shfl_sync(0xffffffffu, myrec, 4 * k + g);
            int c = (int)(rec & 0xffffu);
            __half2 rh = *(__half2*)&rec;
            __half2 w2 = __half2half2(__high2half(rh));   // splat high half
            uint4 hv = *(const uint4*)&d_h[c * 64 + s * 8];
            A0 = __hfma2(*(const __half2*)&hv.x, w2, A0);
            A1 = __hfma2(*(const __half2*)&hv.y, w2, A1);
            A2 = __hfma2(*(const __half2*)&hv.z, w2, A2);
            A3 = __hfma2(*(const __half2*)&hv.w, w2, A3);
        }
        float2 t0 = __half22float2(A0);
        float2 t1 = __half22float2(A1);
        float2 t2 = __half22float2(A2);
        float2 t3 = __half22float2(A3);
        a0 += t0.x; a1 += t0.y;
        a2 += t1.x; a3 += t1.y;
        a4 += t2.x; a5 += t2.y;
        a6 += t3.x; a7 += t3.y;
    }
    // reduce across the 4 groups
#pragma unroll
    for (int o = 8; o <= 16; o <<= 1) {
        a0 += __shfl_xor_sync(0xffffffffu, a0, o);
        a1 += __shfl_xor_sync(0xffffffffu, a1, o);
        a2 += __shfl_xor_sync(0xffffffffu, a2, o);
        a3 += __shfl_xor_sync(0xffffffffu, a3, o);
        a4 += __shfl_xor_sync(0xffffffffu, a4, o);
        a5 += __shfl_xor_sync(0xffffffffu, a5, o);
        a6 += __shfl_xor_sync(0xffffffffu, a6, o);
        a7 += __shfl_xor_sync(0xffffffffu, a7, o);
    }
    if (g == 0) {
        float di = d_dis[node];
        float ws = di * di;                     // self-loop weight (fp32 path)
        uint4 hv = *(const uint4*)&d_h[node * 64 + s * 8];
        float2 f0 = __half22float2(*(const __half2*)&hv.x);
        float2 f1 = __half22float2(*(const __half2*)&hv.y);
        float2 f2 = __half22float2(*(const __half2*)&hv.z);
        float2 f3 = __half22float2(*(const __half2*)&hv.w);
        a0 += f0.x * ws; a1 += f0.y * ws;
        a2 += f1.x * ws; a3 += f1.y * ws;
        a4 += f2.x * ws; a5 += f2.y * ws;
        a6 += f3.x * ws; a7 += f3.y * ws;
        float4 bv0 = *(const float4*)&bias[s * 8];
        float4 bv1 = *(const float4*)&bias[s * 8 + 4];
        a0 = fmaxf(a0 + bv0.x, 0.f); a1 = fmaxf(a1 + bv0.y, 0.f);
        a2 = fmaxf(a2 + bv0.z, 0.f); a3 = fmaxf(a3 + bv0.w, 0.f);
        a4 = fmaxf(a4 + bv1.x, 0.f); a5 = fmaxf(a5 + bv1.y, 0.f);
        a6 = fmaxf(a6 + bv1.z, 0.f); a7 = fmaxf(a7 + bv1.w, 0.f);
        float ss = a0 * a0 + a1 * a1 + a2 * a2 + a3 * a3
                 + a4 * a4 + a5 * a5 + a6 * a6 + a7 * a7;
#pragma unroll
        for (int o = 1; o <= 4; o <<= 1)
            ss += __shfl_xor_sync(0x000000ffu, ss, o);
        float inv = 1.0f / fmaxf(sqrtf(ss), 1e-12f);
        a0 *= inv; a1 *= inv; a2 *= inv; a3 *= inv;
        a4 *= inv; a5 *= inv; a6 *= inv; a7 *= inv;
        __half2 p0 = __floats2half2_rn(a0, a1);
        __half2 p1 = __floats2half2_rn(a2, a3);
        __half2 p2 = __floats2half2_rn(a4, a5);
        __half2 p3 = __floats2half2_rn(a6, a7);
        uint4 ov;
        ov.x = *(unsigned*)&p0; ov.y = *(unsigned*)&p1;
        ov.z = *(unsigned*)&p2; ov.w = *(unsigned*)&p3;
        *(uint4*)&d_emb[node * EMBDIM + loff + s * 8] = ov;
    }
}

// ---------------- final linear + log_softmax --------------------------------
__global__ void __launch_bounds__(256) k_final(const float* __restrict__ Wl,
                                               const float* __restrict__ bl,
                                               float* __restrict__ out) {
    __shared__ __align__(16) float Ws[EMBDIM * CDIM];
    __shared__ float bs[CDIM];
    int tid = threadIdx.x;
    for (int idx = tid; idx < EMBDIM * CDIM; idx += 256) Ws[idx] = Wl[idx];
    if (tid < CDIM) bs[tid] = bl[tid];
    __syncthreads();
    int i = blockIdx.x * 256 + tid;
    if (i >= NNODES) return;
    float acc[CDIM];
#pragma unroll
    for (int j = 0; j < CDIM; j++) acc[j] = bs[j];
    const uint4* erow = (const uint4*)&d_emb[i * EMBDIM];
#pragma unroll 4
    for (int kc = 0; kc < 24; kc++) {          // 24 chunks of 8 halfs
        uint4 hv = erow[kc];
        float2 f[4];
        f[0] = __half22float2(*(const __half2*)&hv.x);
        f[1] = __half22float2(*(const __half2*)&hv.y);
        f[2] = __half22float2(*(const __half2*)&hv.z);
        f[3] = __half22float2(*(const __half2*)&hv.w);
        int kb = kc * 8;
#pragma unroll
        for (int u = 0; u < 4; u++) {
            float ex = f[u].x, ey = f[u].y;
            const float* w0 = &Ws[(kb + 2 * u) * CDIM];
            const float* w1 = w0 + CDIM;
#pragma unroll
            for (int j = 0; j < CDIM; j++)
                acc[j] += ex * w0[j] + ey * w1[j];
        }
    }
    float m = acc[0];
#pragma unroll
    for (int j = 1; j < CDIM; j++) m = fmaxf(m, acc[j]);
    float sum = 0.f;
#pragma unroll
    for (int j = 0; j < CDIM; j++) sum += __expf(acc[j] - m);
    float lse = m + __logf(sum);
#pragma unroll
    for (int j = 0; j < CDIM; j++) out[i * CDIM + j] = acc[j] - lse;
}

// ---------------- launch -----------------------------------------------------
extern "C" void kernel_launch(void* const* d_in, const int* in_sizes, int n_in,
                              void* d_out, int out_size) {
    const float* x    = (const float*)d_in[0];
    const int*   ei   = (const int*)d_in[1];
    const float* W1   = (const float*)d_in[2];
    const float* b1   = (const float*)d_in[3];
    const float* W2   = (const float*)d_in[4];
    const float* b2   = (const float*)d_in[5];
    const float* W3   = (const float*)d_in[6];
    const float* b3   = (const float*)d_in[7];
    const float* Wlin = (const float*)d_in[8];
    const float* blin = (const float*)d_in[9];
    float* out = (float*)d_out;

    const int AGG_BLOCKS = (NNODES + 7) / 8;   // 6250 (8 warps/block)

    // fused: gemm1 (blocks 0..390) + histogram (blocks 391..) in ONE launch
    // (d_count is zero at entry: zero-init at load, self-cleaned by k_scan)
    k_g1hist<<<GEMM_BLOCKS + HIST_BLOCKS, 256>>>(x, W1, ei);
    k_scan<<<1, 1024>>>();
    k_scatter<<<(NEDGES / 2 + 255) / 256, 256>>>(ei);

    k_agg<<<AGG_BLOCKS, 256>>>(b1, 0);
    // layer 2 (fp16 emb slice 0, selected in device code)
    k_gemm<<<GEMM_BLOCKS, 256>>>(nullptr, 0, EMBDIM, W2);
    k_agg<<<AGG_BLOCKS, 256>>>(b2, 64);
    // layer 3 (fp16 emb slice 1)
    k_gemm<<<GEMM_BLOCKS, 256>>>(nullptr, 64, EMBDIM, W3);
    k_agg<<<AGG_BLOCKS, 256>>>(b3, 128);

    k_final<<<(NNODES + 255) / 256, 256>>>(Wlin, blin, out);
}

// round 16
// speedup vs baseline: 1.1939x; 1.0316x over previous
#include <cuda_runtime.h>
#include <cuda_fp16.h>
#include <math.h>

#define NNODES 50000
#define NEDGES 1600000
#define HDIM   64
#define EMBDIM 192
#define CDIM   16
#define NPAD   57344   // 7 * 8192, padded for vectorized scan

#define GEMM_BLOCKS 782                       // ceil(50000/64)
#define HIST_BLOCKS 1563                      // ceil((NEDGES/4)/256)

// ---------------- scratch (static device globals; no allocation) -------------
__device__ __align__(128) __half d_h[NNODES * HDIM];    // per-layer GEMM output (fp16), row = 1 L2 line
__device__ __align__(16) __half d_emb[NNODES * EMBDIM]; // concat of 3 layer outputs (fp16)
__device__ float d_dis[NNODES];                         // D^-1/2
__device__ __align__(16) int d_count[NPAD];
__device__ __align__(16) int d_rowptr[NNODES + 8];
__device__ __align__(16) int d_cursor[NNODES + 8];
__device__ unsigned d_csre[NEDGES];                     // {w_fp16:16 | col:16}

// ---------------- GEMM body: 64 rows per block (occupancy > W-amortization) --
#define XPAD 72
__device__ __forceinline__ void gemm_body(const float* __restrict__ xf,
                                          int inoff, int istride,
                                          const float* __restrict__ W,
                                          int bidx) {
    __shared__ __align__(16) __half Xs[64 * XPAD];
    __shared__ __align__(16) __half Ws[64 * XPAD];
    int tid = threadIdx.x;
    int bm = bidx * 64;

    // load + convert W: thread -> 16 consecutive floats (vectorized)
    {
        int r = tid >> 2, c0 = (tid & 3) * 16;
        const float4* wp = (const float4*)&W[r * 64 + c0];
#pragma unroll
        for (int q = 0; q < 4; q++) {
            float4 wv = wp[q];
            __half2 h0 = __floats2half2_rn(wv.x, wv.y);
            __half2 h1 = __floats2half2_rn(wv.z, wv.w);
            uint2 st; st.x = *(unsigned*)&h0; st.y = *(unsigned*)&h1;
            *(uint2*)&Ws[r * XPAD + c0 + q * 4] = st;
        }
    }
    // load X tile (64 rows)
    if (xf) {
        int r = tid >> 2, c0 = (tid & 3) * 16;
        int gr = bm + r;
        if (gr < NNODES) {
            const float4* xp = (const float4*)&xf[gr * istride + inoff + c0];
#pragma unroll
            for (int q = 0; q < 4; q++) {
                float4 xv = xp[q];
                __half2 h0 = __floats2half2_rn(xv.x, xv.y);
                __half2 h1 = __floats2half2_rn(xv.z, xv.w);
                uint2 st; st.x = *(unsigned*)&h0; st.y = *(unsigned*)&h1;
                *(uint2*)&Xs[r * XPAD + c0 + q * 4] = st;
            }
        } else {
            uint2 z = make_uint2(0u, 0u);
#pragma unroll
            for (int q = 0; q < 4; q++)
                *(uint2*)&Xs[r * XPAD + c0 + q * 4] = z;
        }
    } else {
        const __half* xh = d_emb;   // device-side symbol reference
        int r = tid >> 2, c0 = (tid & 3) * 16;
        int gr = bm + r;
        if (gr < NNODES) {
            const uint4* xp = (const uint4*)&xh[gr * istride + inoff + c0];
            uint4 v0 = xp[0];
            uint4 v1 = xp[1];
            *(uint2*)&Xs[r * XPAD + c0]      = make_uint2(v0.x, v0.y);
            *(uint2*)&Xs[r * XPAD + c0 + 4]  = make_uint2(v0.z, v0.w);
            *(uint2*)&Xs[r * XPAD + c0 + 8]  = make_uint2(v1.x, v1.y);
            *(uint2*)&Xs[r * XPAD + c0 + 12] = make_uint2(v1.z, v1.w);
        } else {
            uint2 z = make_uint2(0u, 0u);
#pragma unroll
            for (int q = 0; q < 4; q++)
                *(uint2*)&Xs[r * XPAD + c0 + q * 4] = z;
        }
    }
    __syncthreads();

    int warp = tid >> 5, lane = tid & 31;
    int Mtile = (warp & 3) * 16;
    int Nbase = (warp >> 2) * 32;

    float acc[4][4];
#pragma unroll
    for (int j = 0; j < 4; j++)
#pragma unroll
        for (int q = 0; q < 4; q++) acc[j][q] = 0.0f;

#pragma unroll
    for (int kk = 0; kk < 4; kk++) {
        unsigned a0, a1, a2, a3;
        {
            int row = Mtile + (lane & 15);
            int col = kk * 16 + (lane >> 4) * 8;
            unsigned addr = (unsigned)__cvta_generic_to_shared(&Xs[row * XPAD + col]);
            asm volatile("ldmatrix.sync.aligned.m8n8.x4.shared.b16 {%0,%1,%2,%3}, [%4];"
                         : "=r"(a0), "=r"(a1), "=r"(a2), "=r"(a3) : "r"(addr));
        }
#pragma unroll
        for (int j = 0; j < 4; j++) {
            int n0 = Nbase + j * 8;
            unsigned b0, b1;
            {
                int row = kk * 16 + (lane & 15);
                unsigned addr = (unsigned)__cvta_generic_to_shared(&Ws[row * XPAD + n0]);
                asm volatile("ldmatrix.sync.aligned.m8n8.x2.trans.shared.b16 {%0,%1}, [%2];"
                             : "=r"(b0), "=r"(b1) : "r"(addr));
            }
            asm volatile("mma.sync.aligned.m16n8k16.row.col.f32.f16.f16.f32 "
                         "{%0,%1,%2,%3},{%4,%5,%6,%7},{%8,%9},{%0,%1,%2,%3};"
                         : "+f"(acc[j][0]), "+f"(acc[j][1]), "+f"(acc[j][2]), "+f"(acc[j][3])
                         : "r"(a0), "r"(a1), "r"(a2), "r"(a3), "r"(b0), "r"(b1));
        }
    }

    // epilogue: write fp16 to d_h
    int r0 = bm + Mtile + (lane >> 2);
    int cb = (lane & 3) * 2;
#pragma unroll
    for (int j = 0; j < 4; j++) {
        int col = Nbase + j * 8 + cb;
        if (r0 < NNODES) {
            __half2 p = __floats2half2_rn(acc[j][0], acc[j][1]);
            *(__half2*)&d_h[r0 * 64 + col] = p;
        }
        if (r0 + 8 < NNODES) {
            __half2 p = __floats2half2_rn(acc[j][2], acc[j][3]);
            *(__half2*)&d_h[(r0 + 8) * 64 + col] = p;
        }
    }
}

// ---------------- fused gemm1 + histogram (independent work, one launch) -----
__global__ void __launch_bounds__(256) k_g1hist(const float* __restrict__ xf,
                                                const float* __restrict__ W,
                                                const int* __restrict__ ei) {
    if (blockIdx.x < GEMM_BLOCKS) {
        gemm_body(xf, 0, HDIM, W, blockIdx.x);
    } else {
        int t = (blockIdx.x - GEMM_BLOCKS) * 256 + threadIdx.x;
        if (t < NEDGES / 4) {
            int4 r = ((const int4*)ei)[t];
            atomicAdd(&d_count[r.x], 1);
            atomicAdd(&d_count[r.y], 1);
            atomicAdd(&d_count[r.z], 1);
            atomicAdd(&d_count[r.w], 1);
        }
    }
}

// standalone GEMM for layers 2/3
__global__ void __launch_bounds__(256) k_gemm(const float* __restrict__ xf,
                                              int inoff, int istride,
                                              const float* __restrict__ W) {
    gemm_body(xf, inoff, istride, W, blockIdx.x);
}

// single-block scan: 1024 threads x 8 elements x 7 tiles (padded counts are 0)
__global__ void __launch_bounds__(1024) k_scan() {
    __shared__ int wsum[32];
    __shared__ int blktot;
    int tid = threadIdx.x;
    int lane = tid & 31, wid = tid >> 5;
    int carry = 0;
#pragma unroll 1
    for (int t = 0; t < 7; t++) {
        int i0 = t * 8192 + tid * 8;
        int4 c0 = *(const int4*)&d_count[i0];
        int4 c1 = *(const int4*)&d_count[i0 + 4];
        int p0 = c0.x;
        int p1 = p0 + c0.y;
        int p2 = p1 + c0.z;
        int p3 = p2 + c0.w;
        int p4 = p3 + c1.x;
        int p5 = p4 + c1.y;
        int p6 = p5 + c1.z;
        int p7 = p6 + c1.w;          // thread total
        int v = p7;
#pragma unroll
        for (int o = 1; o < 32; o <<= 1) {
            int tv = __shfl_up_sync(0xffffffffu, v, o);
            if (lane >= o) v += tv;
        }
        if (lane == 31) wsum[wid] = v;
        __syncthreads();
        if (wid == 0) {
            int w = wsum[lane];
#pragma unroll
            for (int o = 1; o < 32; o <<= 1) {
                int tw = __shfl_up_sync(0xffffffffu, w, o);
                if (lane >= o) w += tw;
            }
            wsum[lane] = w;
            if (lane == 31) blktot = w;
        }
        __syncthreads();
        int base = carry + ((wid > 0) ? wsum[wid - 1] : 0) + (v - p7); // exclusive
        if (i0 < NNODES) {           // NNODES % 8 == 0 -> whole group valid
            int4 r0 = make_int4(base, base + p0, base + p1, base + p2);
            int4 r1 = make_int4(base + p3, base + p4, base + p5, base + p6);
            *(int4*)&d_rowptr[i0]     = r0;
            *(int4*)&d_rowptr[i0 + 4] = r1;
            *(int4*)&d_cursor[i0]     = r0;
            *(int4*)&d_cursor[i0 + 4] = r1;
            float4 q0, q1;
            q0.x = rsqrtf((float)(c0.x + 1)); q0.y = rsqrtf((float)(c0.y + 1));
            q0.z = rsqrtf((float)(c0.z + 1)); q0.w = rsqrtf((float)(c0.w + 1));
            q1.x = rsqrtf((float)(c1.x + 1)); q1.y = rsqrtf((float)(c1.y + 1));
            q1.z = rsqrtf((float)(c1.z + 1)); q1.w = rsqrtf((float)(c1.w + 1));
            *(float4*)&d_dis[i0]     = q0;
            *(float4*)&d_dis[i0 + 4] = q1;
        }
        carry += blktot;
        __syncthreads();
    }
    if (tid == 0) d_rowptr[NNODES] = NEDGES;
}

// scatter packed edge records, 2 edges per thread (NEDGES % 2 == 0)
__global__ void k_scatter(const int* __restrict__ ei) {
    int t = blockIdx.x * blockDim.x + threadIdx.x;
    if (t < NEDGES / 2) {
        int2 r = ((const int2*)ei)[t];
        int2 c = ((const int2*)(ei + NEDGES))[t];
        float w0 = d_dis[r.x] * d_dis[c.x];
        float w1 = d_dis[r.y] * d_dis[c.y];
        unsigned wb0 = (unsigned)__half_as_ushort(__float2half_rn(w0));
        unsigned wb1 = (unsigned)__half_as_ushort(__float2half_rn(w1));
        int p0 = atomicAdd(&d_cursor[r.x], 1);
        d_csre[p0] = (unsigned)c.x | (wb0 << 16);
        int p1 = atomicAdd(&d_cursor[r.y], 1);
        d_csre[p1] = (unsigned)c.y | (wb1 << 16);
    }
}

// ---------------- fused aggregate + self-loop + bias + relu + l2norm --------
// one warp per node, 128-thread blocks (4 warps) -> 16 blocks/SM possible,
// finer HW load-balancing. Records prefetched 32-at-a-time coalesced + shfl
// broadcast; HFMA2 inner accumulation flushed to fp32 per 32-edge chunk.
__global__ void __launch_bounds__(128) k_agg(const float* __restrict__ bias, int loff) {
    int node = (blockIdx.x * blockDim.x + threadIdx.x) >> 5;
    if (node >= NNODES) return;
    int lane = threadIdx.x & 31;
    int g = lane >> 3, s = lane & 7;
    int s0 = d_rowptr[node];
    int cnt = d_rowptr[node + 1] - s0;
    const __half2 hz = __half2half2(__ushort_as_half((unsigned short)0));

    float a0 = 0.f, a1 = 0.f, a2 = 0.f, a3 = 0.f, a4 = 0.f, a5 = 0.f, a6 = 0.f, a7 = 0.f;
    for (int base = 0; base < cnt; base += 32) {
        int m = cnt - base;
        if (m > 32) m = 32;
        unsigned myrec = (lane < m) ? d_csre[s0 + base + lane] : 0u;
        int T = (m + 3) >> 2;                 // warp-uniform trip count (<= 8)
        __half2 A0 = hz, A1 = hz, A2 = hz, A3 = hz;
#pragma unroll 8
        for (int k = 0; k < T; k++) {
            unsigned rec = __shfl_sync(0xffffffffu, myrec, 4 * k + g);
            int c = (int)(rec & 0xffffu);
            __half2 w2 = __half2half2(__ushort_as_half((unsigned short)(rec >> 16)));
            uint4 hv = *(const uint4*)&d_h[c * 64 + s * 8];
            A0 = __hfma2(*(const __half2*)&hv.x, w2, A0);
            A1 = __hfma2(*(const __half2*)&hv.y, w2, A1);
            A2 = __hfma2(*(const __half2*)&hv.z, w2, A2);
            A3 = __hfma2(*(const __half2*)&hv.w, w2, A3);
        }
        float2 t0 = __half22float2(A0);
        float2 t1 = __half22float2(A1);
        float2 t2 = __half22float2(A2);
        float2 t3 = __half22float2(A3);
        a0 += t0.x; a1 += t0.y;
        a2 += t1.x; a3 += t1.y;
        a4 += t2.x; a5 += t2.y;
        a6 += t3.x; a7 += t3.y;
    }
    // reduce across the 4 groups
#pragma unroll
    for (int o = 8; o <= 16; o <<= 1) {
        a0 += __shfl_xor_sync(0xffffffffu, a0, o);
        a1 += __shfl_xor_sync(0xffffffffu, a1, o);
        a2 += __shfl_xor_sync(0xffffffffu, a2, o);
        a3 += __shfl_xor_sync(0xffffffffu, a3, o);
        a4 += __shfl_xor_sync(0xffffffffu, a4, o);
        a5 += __shfl_xor_sync(0xffffffffu, a5, o);
        a6 += __shfl_xor_sync(0xffffffffu, a6, o);
        a7 += __shfl_xor_sync(0xffffffffu, a7, o);
    }
    if (g == 0) {
        float di = d_dis[node];
        float ws = di * di;                     // self-loop weight (fp32 path)
        uint4 hv = *(const uint4*)&d_h[node * 64 + s * 8];
        float2 f0 = __half22float2(*(const __half2*)&hv.x);
        float2 f1 = __half22float2(*(const __half2*)&hv.y);
        float2 f2 = __half22float2(*(const __half2*)&hv.z);
        float2 f3 = __half22float2(*(const __half2*)&hv.w);
        a0 += f0.x * ws; a1 += f0.y * ws;
        a2 += f1.x * ws; a3 += f1.y * ws;
        a4 += f2.x * ws; a5 += f2.y * ws;
        a6 += f3.x * ws; a7 += f3.y * ws;
        float4 bv0 = *(const float4*)&bias[s * 8];
        float4 bv1 = *(const float4*)&bias[s * 8 + 4];
        a0 = fmaxf(a0 + bv0.x, 0.f); a1 = fmaxf(a1 + bv0.y, 0.f);
        a2 = fmaxf(a2 + bv0.z, 0.f); a3 = fmaxf(a3 + bv0.w, 0.f);
        a4 = fmaxf(a4 + bv1.x, 0.f); a5 = fmaxf(a5 + bv1.y, 0.f);
        a6 = fmaxf(a6 + bv1.z, 0.f); a7 = fmaxf(a7 + bv1.w, 0.f);
        float ss = a0 * a0 + a1 * a1 + a2 * a2 + a3 * a3
                 + a4 * a4 + a5 * a5 + a6 * a6 + a7 * a7;
#pragma unroll
        for (int o = 1; o <= 4; o <<= 1)
            ss += __shfl_xor_sync(0x000000ffu, ss, o);
        float inv = 1.0f / fmaxf(sqrtf(ss), 1e-12f);
        a0 *= inv; a1 *= inv; a2 *= inv; a3 *= inv;
        a4 *= inv; a5 *= inv; a6 *= inv; a7 *= inv;
        __half2 p0 = __floats2half2_rn(a0, a1);
        __half2 p1 = __floats2half2_rn(a2, a3);
        __half2 p2 = __floats2half2_rn(a4, a5);
        __half2 p3 = __floats2half2_rn(a6, a7);
        uint4 ov;
        ov.x = *(unsigned*)&p0; ov.y = *(unsigned*)&p1;
        ov.z = *(unsigned*)&p2; ov.w = *(unsigned*)&p3;
        *(uint4*)&d_emb[node * EMBDIM + loff + s * 8] = ov;
    }
}

// ---------------- final linear + log_softmax --------------------------------
__global__ void __launch_bounds__(256) k_final(const float* __restrict__ Wl,
                                               const float* __restrict__ bl,
                                               float* __restrict__ out) {
    __shared__ __align__(16) float Ws[EMBDIM * CDIM];
    __shared__ float bs[CDIM];
    int tid = threadIdx.x;
    for (int idx = tid; idx < EMBDIM * CDIM; idx += 256) Ws[idx] = Wl[idx];
    if (tid < CDIM) bs[tid] = bl[tid];
    __syncthreads();
    int i = blockIdx.x * 256 + tid;
    if (i >= NNODES) return;
    float acc[CDIM];
#pragma unroll
    for (int j = 0; j < CDIM; j++) acc[j] = bs[j];
    const uint4* erow = (const uint4*)&d_emb[i * EMBDIM];
#pragma unroll 4
    for (int kc = 0; kc < 24; kc++) {          // 24 chunks of 8 halfs
        uint4 hv = erow[kc];
        float2 f[4];
        f[0] = __half22float2(*(const __half2*)&hv.x);
        f[1] = __half22float2(*(const __half2*)&hv.y);
        f[2] = __half22float2(*(const __half2*)&hv.z);
        f[3] = __half22float2(*(const __half2*)&hv.w);
        int kb = kc * 8;
#pragma unroll
        for (int u = 0; u < 4; u++) {
            float ex = f[u].x, ey = f[u].y;
            const float* w0 = &Ws[(kb + 2 * u) * CDIM];
            const float* w1 = w0 + CDIM;
#pragma unroll
            for (int j = 0; j < CDIM; j++)
                acc[j] += ex * w0[j] + ey * w1[j];
        }
    }
    float m = acc[0];
#pragma unroll
    for (int j = 1; j < CDIM; j++) m = fmaxf(m, acc[j]);
    float sum = 0.f;
#pragma unroll
    for (int j = 0; j < CDIM; j++) sum += __expf(acc[j] - m);
    float lse = m + __logf(sum);
#pragma unroll
    for (int j = 0; j < CDIM; j++) out[i * CDIM + j] = acc[j] - lse;
}

// ---------------- launch -----------------------------------------------------
extern "C" void kernel_launch(void* const* d_in, const int* in_sizes, int n_in,
                              void* d_out, int out_size) {
    const float* x    = (const float*)d_in[0];
    const int*   ei   = (const int*)d_in[1];
    const float* W1   = (const float*)d_in[2];
    const float* b1   = (const float*)d_in[3];
    const float* W2   = (const float*)d_in[4];
    const float* b2   = (const float*)d_in[5];
    const float* W3   = (const float*)d_in[6];
    const float* b3   = (const float*)d_in[7];
    const float* Wlin = (const float*)d_in[8];
    const float* blin = (const float*)d_in[9];
    float* out = (float*)d_out;

    void* count_ptr = nullptr;
    cudaGetSymbolAddress(&count_ptr, d_count);
    cudaMemsetAsync(count_ptr, 0, NPAD * sizeof(int), 0);

    const int AGG_BLOCKS = (NNODES + 3) / 4;   // 12500 (4 warps/block, 128 thr)

    // fused: gemm1 (blocks 0..781) + histogram (blocks 782..) in ONE launch
    k_g1hist<<<GEMM_BLOCKS + HIST_BLOCKS, 256>>>(x, W1, ei);
    k_scan<<<1, 1024>>>();
    k_scatter<<<(NEDGES / 2 + 255) / 256, 256>>>(ei);

    k_agg<<<AGG_BLOCKS, 128>>>(b1, 0);
    // layer 2 (fp16 emb slice 0, selected in device code)
    k_gemm<<<GEMM_BLOCKS, 256>>>(nullptr, 0, EMBDIM, W2);
    k_agg<<<AGG_BLOCKS, 128>>>(b2, 64);
    // layer 3 (fp16 emb slice 1)
    k_gemm<<<GEMM_BLOCKS, 256>>>(nullptr, 64, EMBDIM, W3);
    k_agg<<<AGG_BLOCKS, 128>>>(b3, 128);

    k_final<<<(NNODES + 255) / 256, 256>>>(Wlin, blin, out);
}